// round 11
// baseline (speedup 1.0000x reference)
#include <cuda_runtime.h>
#include <math.h>
#include <stdint.h>

// ---------------------------------------------------------------------------
// Problem constants
// ---------------------------------------------------------------------------
#define SEQ    4096
#define DM     1024
#define NIMU   72
#define NNOISE 12
#define NOUT   (NIMU * NNOISE)   // 864
#define TSTEPS 300
#define NM     (NIMU * SEQ)      // 294912

// ---------------------------------------------------------------------------
// Scratch (static device globals; no allocation allowed)
// ---------------------------------------------------------------------------
__device__ __align__(16) float  g_mu[SEQ];
__device__ __align__(16) float  g_rstd[SEQ];
__device__ __align__(16) float  g_gamma[DM];
__device__ __align__(16) float  g_beta[DM];
__device__ __align__(16) float  g_bprime[NOUT];
__device__ __align__(16) float  g_p[SEQ * NOUT];           // 14.2 MB
__device__ float2 g_X0[NM], g_Y0[NM], g_A[NM], g_B[NM];    // 9.4 MB

// ---------------------------------------------------------------------------
// Helpers
// ---------------------------------------------------------------------------
typedef unsigned long long ull;

__device__ __forceinline__ ull pk2(float lo, float hi) {
    ull r;
    asm("mov.b64 %0, {%1, %2};" : "=l"(r) : "f"(lo), "f"(hi));
    return r;
}
__device__ __forceinline__ void upk2(float& lo, float& hi, ull v) {
    asm("mov.b64 {%0, %1}, %2;" : "=f"(lo), "=f"(hi) : "l"(v));
}
#define FMA2(d, a, b, c) asm("fma.rn.f32x2 %0, %1, %2, %3;" : "=l"(d) : "l"(a), "l"(b), "l"(c))
#define MUL2(d, a, b)    asm("mul.rn.f32x2 %0, %1, %2;"     : "=l"(d) : "l"(a), "l"(b))

__device__ __forceinline__ float softplus_f(float x) {
    return fmaxf(x, 0.0f) + log1pf(expf(-fabsf(x)));
}
__device__ __forceinline__ float to_tf32(float x) {
    float r;
    asm("cvt.rna.tf32.f32 %0, %1;" : "=f"(r) : "f"(x));
    return r;
}
// m16n8k8 tf32 warp MMA, fp32 accumulate (baseline PTX, sm_80+)
__device__ __forceinline__ void mma8(float* d, const uint32_t* a, uint32_t b0, uint32_t b1) {
    asm volatile(
        "mma.sync.aligned.m16n8k8.row.col.f32.tf32.tf32.f32 "
        "{%0,%1,%2,%3}, {%4,%5,%6,%7}, {%8,%9}, {%0,%1,%2,%3};"
        : "+f"(d[0]), "+f"(d[1]), "+f"(d[2]), "+f"(d[3])
        : "r"(a[0]), "r"(a[1]), "r"(a[2]), "r"(a[3]), "r"(b0), "r"(b1));
}

// ---------------------------------------------------------------------------
// 0) Disambiguate LN vectors (gamma≈ones, beta≈zeros)
// ---------------------------------------------------------------------------
__global__ __launch_bounds__(256) void pick_ln_kernel(const float* __restrict__ a,
                                                      const float* __restrict__ b) {
    __shared__ float sA, sB;
    const int tid = threadIdx.x;
    if (tid == 0) { sA = 0.0f; sB = 0.0f; }
    __syncthreads();
    float la = 0.0f, lb = 0.0f;
    for (int k = tid; k < DM; k += 256) {
        float av = a[k], bv = b[k];
        la += (av - 1.0f) * (av - 1.0f) + bv * bv;
        lb += (bv - 1.0f) * (bv - 1.0f) + av * av;
    }
    #pragma unroll
    for (int o = 16; o > 0; o >>= 1) {
        la += __shfl_down_sync(0xffffffffu, la, o);
        lb += __shfl_down_sync(0xffffffffu, lb, o);
    }
    if ((tid & 31) == 0) { atomicAdd(&sA, la); atomicAdd(&sB, lb); }
    __syncthreads();
    const bool swap = sB < sA;
    for (int k = tid; k < DM; k += 256) {
        g_gamma[k] = swap ? b[k] : a[k];
        g_beta[k]  = swap ? a[k] : b[k];
    }
}

// ---------------------------------------------------------------------------
// 1) Per-token mean / rstd
// ---------------------------------------------------------------------------
__global__ __launch_bounds__(256) void stats_kernel(const float* __restrict__ x) {
    __shared__ float ss[8], ss2[8];
    const int row = blockIdx.x;
    const int tid = threadIdx.x;
    float4 v = reinterpret_cast<const float4*>(x + (size_t)row * DM)[tid];
    float s  = v.x + v.y + v.z + v.w;
    float s2 = v.x * v.x + v.y * v.y + v.z * v.z + v.w * v.w;
    #pragma unroll
    for (int o = 16; o > 0; o >>= 1) {
        s  += __shfl_down_sync(0xffffffffu, s,  o);
        s2 += __shfl_down_sync(0xffffffffu, s2, o);
    }
    if ((tid & 31) == 0) { ss[tid >> 5] = s; ss2[tid >> 5] = s2; }
    __syncthreads();
    if (tid < 8) {
        s = ss[tid]; s2 = ss2[tid];
        #pragma unroll
        for (int o = 4; o > 0; o >>= 1) {
            s  += __shfl_down_sync(0xffu, s,  o);
            s2 += __shfl_down_sync(0xffu, s2, o);
        }
        if (tid == 0) {
            float mu  = s * (1.0f / DM);
            float var = s2 * (1.0f / DM) - mu * mu;
            g_mu[row]   = mu;
            g_rstd[row] = 1.0f / sqrtf(var + 1e-5f);
        }
    }
}

// ---------------------------------------------------------------------------
// 2) bprime[n] = b[n] + sum_k beta[k] * W[k][n]
// ---------------------------------------------------------------------------
__global__ __launch_bounds__(256) void bprime_kernel(const float* __restrict__ W,
                                                     const float* __restrict__ b) {
    __shared__ float sred[8][32];
    const int tid  = threadIdx.x;
    const int lane = tid & 31;
    const int w    = tid >> 5;
    const int col  = blockIdx.x * 32 + lane;
    float acc = 0.0f;
    #pragma unroll 8
    for (int k = w; k < DM; k += 8)
        acc = fmaf(g_beta[k], W[(size_t)k * NOUT + col], acc);
    sred[w][lane] = acc;
    __syncthreads();
    if (w == 0) {
        float tot = b[col];
        #pragma unroll
        for (int j = 0; j < 8; j++) tot += sred[j][lane];
        g_bprime[col] = tot;
    }
}

// ---------------------------------------------------------------------------
// 3) GEMM via mma.sync tf32 (3-pass split), fused LN on A.
//    BM=256, BN=96, BK=32; grid 16x9 = 144 blocks = ONE WAVE; 512 threads.
//    16 warps: consumers 8(M)x2(N), warp tile 32x48. Fragments in smem:
//    slotA = (mf*4+ks)*32+lane (mf=row/16, 0..15), slotB = (nf*4+ks)*32+lane
//    (nf=col/8, 0..11). AH/AL: 4 floats/slot; BF: {b0h,b1h,b0l,b1l}.
// ---------------------------------------------------------------------------
#define BM 256
#define BN 96
#define BK 32
#define GN_ITER (DM / BK)    // 32
#define SM_AH 0              // 8192 floats
#define SM_AL 8192           // 8192 floats
#define SM_BF 16384          // 6144 floats
#define SM_FLOATS 22528      // 90112 bytes

__global__ __launch_bounds__(512, 1) void gemm_mma_kernel(const float* __restrict__ x,
                                                          const float* __restrict__ W) {
    extern __shared__ float sm[];
    const int tid  = threadIdx.x;
    const int w    = tid >> 5;
    const int lane = tid & 31;
    const int g    = lane >> 2;
    const int tg   = lane & 3;
    const int bm   = blockIdx.x * BM;
    const int bn   = blockIdx.y * BN;

    // producer role
    const int ksP     = w & 3;
    const int quarter = w >> 2;        // 0..3
    // consumer role
    const int wm = w & 7;              // 0..7 -> 32-row tile
    const int wn = w >> 3;             // 0..1 -> 48-col tile

    // hoisted LN stats for producer rows (mf = q*4+quarter, rows mf*16+g, +8)
    float muA[4][2], rsA[4][2];
    #pragma unroll
    for (int q = 0; q < 4; q++) {
        int m0 = (q * 4 + quarter) * 16 + g;
        muA[q][0] = g_mu[bm + m0];     rsA[q][0] = g_rstd[bm + m0];
        muA[q][1] = g_mu[bm + m0 + 8]; rsA[q][1] = g_rstd[bm + m0 + 8];
    }

    float acc[2][6][4];
    #pragma unroll
    for (int mi = 0; mi < 2; mi++)
        #pragma unroll
        for (int j = 0; j < 6; j++)
            #pragma unroll
            for (int r = 0; r < 4; r++) acc[mi][j][r] = 0.0f;

    for (int it = 0; it < GN_ITER; it++) {
        const int kc0 = it * BK + ksP * 8 + tg;
        const int kc1 = kc0 + 4;
        const float pg0 = g_gamma[kc0];
        const float pg1 = g_gamma[kc1];

        // ---- A: load, normalize, split hi/lo, store fragments ----
        #pragma unroll
        for (int q = 0; q < 4; q++) {
            const int mf = q * 4 + quarter;
            const float* xr0 = x + (size_t)(bm + mf * 16 + g) * DM;
            const float* xr1 = xr0 + 8 * DM;
            float n0 = (xr0[kc0] - muA[q][0]) * rsA[q][0] * pg0;
            float n1 = (xr1[kc0] - muA[q][1]) * rsA[q][1] * pg0;
            float n2 = (xr0[kc1] - muA[q][0]) * rsA[q][0] * pg1;
            float n3 = (xr1[kc1] - muA[q][1]) * rsA[q][1] * pg1;
            float4 h, l;
            h.x = to_tf32(n0); h.y = to_tf32(n1);
            h.z = to_tf32(n2); h.w = to_tf32(n3);
            l.x = to_tf32(n0 - h.x); l.y = to_tf32(n1 - h.y);
            l.z = to_tf32(n2 - h.z); l.w = to_tf32(n3 - h.w);
            const int slot = (mf * 4 + ksP) * 32 + lane;
            *(float4*)&sm[SM_AH + slot * 4] = h;
            *(float4*)&sm[SM_AL + slot * 4] = l;
        }
        // ---- B: load, split hi/lo, store fragments ----
        #pragma unroll
        for (int q = 0; q < 3; q++) {
            const int nf = q * 4 + quarter;
            const int n  = bn + nf * 8 + g;
            float b0 = W[(size_t)kc0 * NOUT + n];
            float b1 = W[(size_t)kc1 * NOUT + n];
            float4 v;
            v.x = to_tf32(b0); v.y = to_tf32(b1);
            v.z = to_tf32(b0 - v.x); v.w = to_tf32(b1 - v.y);
            const int slot = (nf * 4 + ksP) * 32 + lane;
            *(float4*)&sm[SM_BF + slot * 4] = v;
        }
        __syncthreads();

        // ---- compute: 4 ks x (2 mi x 6 j x 3 passes) ----
        #pragma unroll
        for (int ks = 0; ks < 4; ks++) {
            uint32_t bf[6][4];
            #pragma unroll
            for (int j = 0; j < 6; j++) {
                int slot = ((wn * 6 + j) * 4 + ks) * 32 + lane;
                *(float4*)&bf[j][0] = *(const float4*)&sm[SM_BF + slot * 4];
            }
            #pragma unroll
            for (int mi = 0; mi < 2; mi++) {
                int slot = ((wm * 2 + mi) * 4 + ks) * 32 + lane;
                uint32_t Ah[4], Al[4];
                *(float4*)&Ah[0] = *(const float4*)&sm[SM_AH + slot * 4];
                *(float4*)&Al[0] = *(const float4*)&sm[SM_AL + slot * 4];
                #pragma unroll
                for (int j = 0; j < 6; j++) {
                    mma8(acc[mi][j], Ah, bf[j][0], bf[j][1]);   // Ah*Bh
                    mma8(acc[mi][j], Ah, bf[j][2], bf[j][3]);   // Ah*Bl
                    mma8(acc[mi][j], Al, bf[j][0], bf[j][1]);   // Al*Bh
                }
            }
        }
        __syncthreads();
    }

    // Epilogue: + bprime, store
    #pragma unroll
    for (int mi = 0; mi < 2; mi++) {
        const int row0 = bm + wm * 32 + mi * 16 + g;
        #pragma unroll
        for (int j = 0; j < 6; j++) {
            const int col = bn + wn * 48 + j * 8 + 2 * tg;
            float bp0 = g_bprime[col], bp1 = g_bprime[col + 1];
            *(float2*)&g_p[(size_t)row0 * NOUT + col] =
                make_float2(acc[mi][j][0] + bp0, acc[mi][j][1] + bp1);
            *(float2*)&g_p[(size_t)(row0 + 8) * NOUT + col] =
                make_float2(acc[mi][j][2] + bp0, acc[mi][j][3] + bp1);
        }
    }
}

// ---------------------------------------------------------------------------
// 4) Epilogue: tile 8 seq-rows of p through smem (coalesced), derive spring
//    params + 4 aux outputs.
// ---------------------------------------------------------------------------
__global__ __launch_bounds__(256) void epi_kernel(float* __restrict__ out, int full_out) {
    __shared__ float sp[8 * NOUT];
    const int s0  = blockIdx.x * 8;
    const int tid = threadIdx.x;

    const float4* src = (const float4*)(g_p + (size_t)s0 * NOUT);
    for (int v = tid; v < 8 * NOUT / 4; v += 256)
        ((float4*)sp)[v] = src[v];
    __syncthreads();

    for (int v = tid; v < 8 * NIMU; v += 256) {
        const int i  = v >> 3;
        const int sl = v & 7;
        const int s  = s0 + sl;
        const float* pr = &sp[sl * NOUT];

        float p0  = pr[0 * NIMU + i];
        float p1  = pr[1 * NIMU + i];
        float p2  = pr[2 * NIMU + i];
        float p3  = pr[3 * NIMU + i];
        float c   = pr[4 * NIMU + i];
        float ct  = pr[5 * NIMU + i];
        float phi = pr[6 * NIMU + i];
        float pht = pr[7 * NIMU + i];

        float d  = softplus_f(p1);
        float dt = softplus_f(p3);
        float w1 = sqrtf(softplus_f(p0));
        float w2 = sqrtf(softplus_f(p2));
        float e1 = __expf(-0.5f * d);
        float e2 = __expf(-0.5f * dt);

        float sph, cph, spt, cpt, sw1, cw1, sw2, cw2;
        __sincosf(phi, &sph, &cph);
        __sincosf(pht, &spt, &cpt);
        sincosf(w1, &sw1, &cw1);
        sincosf(w2, &sw2, &cw2);

        const int j = i * SEQ + s;
        g_X0[j] = make_float2(c * cph, ct * cpt);
        g_Y0[j] = make_float2(c * sph, ct * spt);
        g_A[j]  = make_float2(e1 * cw1, e2 * cw2);
        g_B[j]  = make_float2(e1 * sw1, e2 * sw2);

        if (full_out) {
            out[1 * NM + j] = pr[8 * NIMU + i];
            out[2 * NM + j] = softplus_f(pr[9 * NIMU + i]);
            out[3 * NM + j] = pr[10 * NIMU + i];
            out[4 * NM + j] = softplus_f(pr[11 * NIMU + i]);
        }
    }
}

// ---------------------------------------------------------------------------
// 5) Zero kinematics region
// ---------------------------------------------------------------------------
__global__ __launch_bounds__(256) void zero_kernel(float* __restrict__ out) {
    int j = blockIdx.x * 256 + threadIdx.x;
    if (j * 4 < NM) ((float4*)out)[j] = make_float4(0.f, 0.f, 0.f, 0.f);
}

// ---------------------------------------------------------------------------
// 6) Spring + diagonal scatter — rotating-accumulator wavefront (proven).
// ---------------------------------------------------------------------------
__global__ __launch_bounds__(256) void spring_kernel(float* __restrict__ out) {
    __shared__ float sbuf[8][336];

    const int i    = blockIdx.y;
    const int s0   = blockIdx.x * 256;
    const int tid  = threadIdx.x;
    const int w    = tid >> 5;
    const int lane = tid & 31;

    const int s   = s0 + w * 32 + lane;
    const int idx = i * SEQ + s;
    float2 x0 = g_X0[idx], y0 = g_Y0[idx], av = g_A[idx], bv = g_B[idx];
    ull X  = pk2(x0.x, x0.y);
    ull Y  = pk2(y0.x, y0.y);
    ull A  = pk2(av.x, av.y);
    ull B  = pk2(bv.x, bv.y);
    ull Bn = pk2(-bv.x, -bv.y);

    float* buf = &sbuf[w][0];
    float acc = 0.0f;
    int   src = lane;
    int   fl  = -1;

    #pragma unroll 4
    for (int t = 0; t < TSTEPS; t++) {
        float lo, hi;
        upk2(lo, hi, Y);
        float c = lo + hi;
        float r = __shfl_sync(0xffffffffu, c, src);
        if (fl == lane) { buf[t - 1] = acc; acc = 0.0f; }
        acc += r;
        ull u, v, Xn;
        MUL2(u, Y, Bn);
        FMA2(Xn, X, A, u);
        MUL2(v, X, B);
        FMA2(Y, Y, A, v);
        X = Xn;
        src = (src + 31) & 31;
        fl  = (fl + 1) & 31;
    }
    {
        int p = (TSTEPS - 1) + ((lane - ((TSTEPS - 1) & 31)) & 31);
        buf[p] = acc;
    }
    __syncthreads();

    for (int q = tid; q < 555; q += 256) {
        float tot = 0.0f;
        #pragma unroll
        for (int w2 = 0; w2 < 8; w2++) {
            int r = q - 32 * w2;
            if (r >= 0 && r < 331) tot += sbuf[w2][r];
        }
        int pos = s0 + q;
        if (pos < SEQ) atomicAdd(&out[i * SEQ + pos], tot);
    }
}

// ---------------------------------------------------------------------------
// Launch — inputs identified by size
// ---------------------------------------------------------------------------
extern "C" void kernel_launch(void* const* d_in, const int* in_sizes, int n_in,
                              void* d_out, int out_size) {
    const float* x  = nullptr;
    const float* W  = nullptr;
    const float* b  = nullptr;
    const float* v1 = nullptr;
    const float* v2 = nullptr;
    for (int idx = 0; idx < n_in; idx++) {
        int sz = in_sizes[idx];
        const float* p = (const float*)d_in[idx];
        if      (sz == SEQ * DM)   x = p;
        else if (sz == DM * NOUT)  W = p;
        else if (sz == NOUT)       b = p;
        else if (sz == DM)         { if (!v1) v1 = p; else v2 = p; }
    }
    float* out = (float*)d_out;
    int full_out = (out_size >= 5 * NM) ? 1 : 0;

    cudaFuncSetAttribute(gemm_mma_kernel,
                         cudaFuncAttributeMaxDynamicSharedMemorySize,
                         SM_FLOATS * (int)sizeof(float));

    pick_ln_kernel<<<1, 256>>>(v1, v2);
    stats_kernel<<<SEQ, 256>>>(x);
    bprime_kernel<<<NOUT / 32, 256>>>(W, b);
    gemm_mma_kernel<<<dim3(SEQ / BM, NOUT / BN), 512,
                      SM_FLOATS * sizeof(float)>>>(x, W);
    epi_kernel<<<SEQ / 8, 256>>>(out, full_out);
    zero_kernel<<<(NM / 4 + 255) / 256, 256>>>(out);
    spring_kernel<<<dim3(SEQ / 256, NIMU), 256>>>(out);
}

// round 13
// speedup vs baseline: 1.1148x; 1.1148x over previous
#include <cuda_runtime.h>
#include <math.h>
#include <stdint.h>

// ---------------------------------------------------------------------------
// Problem constants
// ---------------------------------------------------------------------------
#define SEQ    4096
#define DM     1024
#define NIMU   72
#define NNOISE 12
#define NOUT   (NIMU * NNOISE)   // 864
#define TSTEPS 300
#define NM     (NIMU * SEQ)      // 294912

// ---------------------------------------------------------------------------
// Scratch (static device globals; no allocation allowed)
// ---------------------------------------------------------------------------
__device__ __align__(16) float  g_mu[SEQ];
__device__ __align__(16) float  g_rstd[SEQ];
__device__ __align__(16) float  g_gamma[DM];
__device__ __align__(16) float  g_beta[DM];
__device__ __align__(16) float  g_bprime[NOUT];
__device__ __align__(16) float  g_p[SEQ * NOUT];           // 14.2 MB
__device__ float2 g_X0[NM], g_Y0[NM], g_A[NM], g_B[NM];    // 9.4 MB

// ---------------------------------------------------------------------------
// Helpers
// ---------------------------------------------------------------------------
typedef unsigned long long ull;

__device__ __forceinline__ ull pk2(float lo, float hi) {
    ull r;
    asm("mov.b64 %0, {%1, %2};" : "=l"(r) : "f"(lo), "f"(hi));
    return r;
}
__device__ __forceinline__ void upk2(float& lo, float& hi, ull v) {
    asm("mov.b64 {%0, %1}, %2;" : "=f"(lo), "=f"(hi) : "l"(v));
}
#define FMA2(d, a, b, c) asm("fma.rn.f32x2 %0, %1, %2, %3;" : "=l"(d) : "l"(a), "l"(b), "l"(c))
#define MUL2(d, a, b)    asm("mul.rn.f32x2 %0, %1, %2;"     : "=l"(d) : "l"(a), "l"(b))

__device__ __forceinline__ float softplus_f(float x) {
    return fmaxf(x, 0.0f) + log1pf(expf(-fabsf(x)));
}
__device__ __forceinline__ float to_tf32(float x) {
    float r;
    asm("cvt.rna.tf32.f32 %0, %1;" : "=f"(r) : "f"(x));
    return r;
}
// m16n8k8 tf32 warp MMA, fp32 accumulate (baseline PTX, sm_80+)
__device__ __forceinline__ void mma8(float* d, const uint32_t* a, uint32_t b0, uint32_t b1) {
    asm volatile(
        "mma.sync.aligned.m16n8k8.row.col.f32.tf32.tf32.f32 "
        "{%0,%1,%2,%3}, {%4,%5,%6,%7}, {%8,%9}, {%0,%1,%2,%3};"
        : "+f"(d[0]), "+f"(d[1]), "+f"(d[2]), "+f"(d[3])
        : "r"(a[0]), "r"(a[1]), "r"(a[2]), "r"(a[3]), "r"(b0), "r"(b1));
}

// ---------------------------------------------------------------------------
// 0) Disambiguate LN vectors (gamma≈ones, beta≈zeros)
// ---------------------------------------------------------------------------
__global__ __launch_bounds__(256) void pick_ln_kernel(const float* __restrict__ a,
                                                      const float* __restrict__ b) {
    __shared__ float sA, sB;
    const int tid = threadIdx.x;
    if (tid == 0) { sA = 0.0f; sB = 0.0f; }
    __syncthreads();
    float la = 0.0f, lb = 0.0f;
    for (int k = tid; k < DM; k += 256) {
        float av = a[k], bv = b[k];
        la += (av - 1.0f) * (av - 1.0f) + bv * bv;
        lb += (bv - 1.0f) * (bv - 1.0f) + av * av;
    }
    #pragma unroll
    for (int o = 16; o > 0; o >>= 1) {
        la += __shfl_down_sync(0xffffffffu, la, o);
        lb += __shfl_down_sync(0xffffffffu, lb, o);
    }
    if ((tid & 31) == 0) { atomicAdd(&sA, la); atomicAdd(&sB, lb); }
    __syncthreads();
    const bool swap = sB < sA;
    for (int k = tid; k < DM; k += 256) {
        g_gamma[k] = swap ? b[k] : a[k];
        g_beta[k]  = swap ? a[k] : b[k];
    }
}

// ---------------------------------------------------------------------------
// 1) Per-token mean / rstd
// ---------------------------------------------------------------------------
__global__ __launch_bounds__(256) void stats_kernel(const float* __restrict__ x) {
    __shared__ float ss[8], ss2[8];
    const int row = blockIdx.x;
    const int tid = threadIdx.x;
    float4 v = reinterpret_cast<const float4*>(x + (size_t)row * DM)[tid];
    float s  = v.x + v.y + v.z + v.w;
    float s2 = v.x * v.x + v.y * v.y + v.z * v.z + v.w * v.w;
    #pragma unroll
    for (int o = 16; o > 0; o >>= 1) {
        s  += __shfl_down_sync(0xffffffffu, s,  o);
        s2 += __shfl_down_sync(0xffffffffu, s2, o);
    }
    if ((tid & 31) == 0) { ss[tid >> 5] = s; ss2[tid >> 5] = s2; }
    __syncthreads();
    if (tid < 8) {
        s = ss[tid]; s2 = ss2[tid];
        #pragma unroll
        for (int o = 4; o > 0; o >>= 1) {
            s  += __shfl_down_sync(0xffu, s,  o);
            s2 += __shfl_down_sync(0xffu, s2, o);
        }
        if (tid == 0) {
            float mu  = s * (1.0f / DM);
            float var = s2 * (1.0f / DM) - mu * mu;
            g_mu[row]   = mu;
            g_rstd[row] = 1.0f / sqrtf(var + 1e-5f);
        }
    }
}

// ---------------------------------------------------------------------------
// 2) bprime[n] = b[n] + sum_k beta[k] * W[k][n]
// ---------------------------------------------------------------------------
__global__ __launch_bounds__(256) void bprime_kernel(const float* __restrict__ W,
                                                     const float* __restrict__ b) {
    __shared__ float sred[8][32];
    const int tid  = threadIdx.x;
    const int lane = tid & 31;
    const int w    = tid >> 5;
    const int col  = blockIdx.x * 32 + lane;
    float acc = 0.0f;
    #pragma unroll 8
    for (int k = w; k < DM; k += 8)
        acc = fmaf(g_beta[k], W[(size_t)k * NOUT + col], acc);
    sred[w][lane] = acc;
    __syncthreads();
    if (w == 0) {
        float tot = b[col];
        #pragma unroll
        for (int j = 0; j < 8; j++) tot += sred[j][lane];
        g_bprime[col] = tot;
    }
}

// ---------------------------------------------------------------------------
// 3) GEMM via mma.sync tf32 (3-pass split), fused LN on A.
//    BM=128, BN=96, BK=32; grid 32x9 = 288 blocks; 256 threads.
//    __launch_bounds__(256,2) -> <=128 regs -> 2 blocks/SM co-resident:
//    cross-block phase overlap hides L2 latency (no reg prefetch needed).
//    Fragments in smem: slotA = (mf*4+ks)*32+lane (mf=row/16, 0..7),
//    slotB = (nf*4+ks)*32+lane (nf=col/8, 0..11). AH/AL 4 floats/slot;
//    BF {b0h,b1h,b0l,b1l}.
// ---------------------------------------------------------------------------
#define BM 128
#define BN 96
#define BK 32
#define GN_ITER (DM / BK)    // 32
#define SM_AH 0              // 4096 floats
#define SM_AL 4096           // 4096 floats
#define SM_BF 8192           // 6144 floats
#define SM_FLOATS 14336      // 57344 bytes

__global__ __launch_bounds__(256, 2) void gemm_mma_kernel(const float* __restrict__ x,
                                                          const float* __restrict__ W) {
    extern __shared__ float sm[];
    const int tid  = threadIdx.x;
    const int w    = tid >> 5;
    const int lane = tid & 31;
    const int g    = lane >> 2;
    const int tg   = lane & 3;
    const int bm   = blockIdx.x * BM;
    const int bn   = blockIdx.y * BN;

    // producer role: ks = w&3, half = w>>2 (0..1)
    const int ksP  = w & 3;
    const int half = w >> 2;
    // consumer role: warp tile (wm*32 rows) x (wn*48 cols)
    const int wm = w & 3;
    const int wn = w >> 2;

    // hoisted LN stats for producer A rows (mf = 2q+half, rows mf*16+g, +8)
    float muA[4][2], rsA[4][2];
    #pragma unroll
    for (int q = 0; q < 4; q++) {
        int m0 = (2 * q + half) * 16 + g;
        muA[q][0] = g_mu[bm + m0];     rsA[q][0] = g_rstd[bm + m0];
        muA[q][1] = g_mu[bm + m0 + 8]; rsA[q][1] = g_rstd[bm + m0 + 8];
    }

    float acc[2][6][4];
    #pragma unroll
    for (int mi = 0; mi < 2; mi++)
        #pragma unroll
        for (int j = 0; j < 6; j++)
            #pragma unroll
            for (int r = 0; r < 4; r++) acc[mi][j][r] = 0.0f;

    for (int it = 0; it < GN_ITER; it++) {
        const int kc0 = it * BK + ksP * 8 + tg;
        const int kc1 = kc0 + 4;
        const float pg0 = g_gamma[kc0];
        const float pg1 = g_gamma[kc1];

        // ---- A: load + normalize + split + store fragment (fused, low-reg) ----
        #pragma unroll
        for (int q = 0; q < 4; q++) {
            const int mf = 2 * q + half;
            const float* xr0 = x + (size_t)(bm + mf * 16 + g) * DM;
            const float* xr1 = xr0 + 8 * DM;
            float n0 = (xr0[kc0] - muA[q][0]) * rsA[q][0] * pg0;
            float n1 = (xr1[kc0] - muA[q][1]) * rsA[q][1] * pg0;
            float n2 = (xr0[kc1] - muA[q][0]) * rsA[q][0] * pg1;
            float n3 = (xr1[kc1] - muA[q][1]) * rsA[q][1] * pg1;
            float4 h, l;
            h.x = to_tf32(n0); h.y = to_tf32(n1);
            h.z = to_tf32(n2); h.w = to_tf32(n3);
            l.x = to_tf32(n0 - h.x); l.y = to_tf32(n1 - h.y);
            l.z = to_tf32(n2 - h.z); l.w = to_tf32(n3 - h.w);
            const int slot = (mf * 4 + ksP) * 32 + lane;
            *(float4*)&sm[SM_AH + slot * 4] = h;
            *(float4*)&sm[SM_AL + slot * 4] = l;
        }
        // ---- B: load + split + store fragment ----
        #pragma unroll
        for (int q = 0; q < 6; q++) {
            const int nf = 2 * q + half;
            const int n  = bn + nf * 8 + g;
            float b0 = W[(size_t)kc0 * NOUT + n];
            float b1 = W[(size_t)kc1 * NOUT + n];
            float4 v;
            v.x = to_tf32(b0); v.y = to_tf32(b1);
            v.z = to_tf32(b0 - v.x); v.w = to_tf32(b1 - v.y);
            const int slot = (nf * 4 + ksP) * 32 + lane;
            *(float4*)&sm[SM_BF + slot * 4] = v;
        }
        __syncthreads();

        // ---- compute: 4 ks x (2 mi x 6 j x 3 passes) ----
        #pragma unroll
        for (int ks = 0; ks < 4; ks++) {
            uint32_t bf[6][4];
            #pragma unroll
            for (int j = 0; j < 6; j++) {
                int slot = ((wn * 6 + j) * 4 + ks) * 32 + lane;
                *(float4*)&bf[j][0] = *(const float4*)&sm[SM_BF + slot * 4];
            }
            #pragma unroll
            for (int mi = 0; mi < 2; mi++) {
                int slot = ((wm * 2 + mi) * 4 + ks) * 32 + lane;
                uint32_t Ah[4], Al[4];
                *(float4*)&Ah[0] = *(const float4*)&sm[SM_AH + slot * 4];
                *(float4*)&Al[0] = *(const float4*)&sm[SM_AL + slot * 4];
                #pragma unroll
                for (int j = 0; j < 6; j++) {
                    mma8(acc[mi][j], Ah, bf[j][0], bf[j][1]);   // Ah*Bh
                    mma8(acc[mi][j], Ah, bf[j][2], bf[j][3]);   // Ah*Bl
                    mma8(acc[mi][j], Al, bf[j][0], bf[j][1]);   // Al*Bh
                }
            }
        }
        __syncthreads();
    }

    // Epilogue: + bprime, store
    #pragma unroll
    for (int mi = 0; mi < 2; mi++) {
        const int row0 = bm + wm * 32 + mi * 16 + g;
        #pragma unroll
        for (int j = 0; j < 6; j++) {
            const int col = bn + wn * 48 + j * 8 + 2 * tg;
            float bp0 = g_bprime[col], bp1 = g_bprime[col + 1];
            *(float2*)&g_p[(size_t)row0 * NOUT + col] =
                make_float2(acc[mi][j][0] + bp0, acc[mi][j][1] + bp1);
            *(float2*)&g_p[(size_t)(row0 + 8) * NOUT + col] =
                make_float2(acc[mi][j][2] + bp0, acc[mi][j][3] + bp1);
        }
    }
}

// ---------------------------------------------------------------------------
// 4) Epilogue: tile 8 seq-rows of p through smem (coalesced), derive spring
//    params + 4 aux outputs.
// ---------------------------------------------------------------------------
__global__ __launch_bounds__(256) void epi_kernel(float* __restrict__ out, int full_out) {
    __shared__ float sp[8 * NOUT];
    const int s0  = blockIdx.x * 8;
    const int tid = threadIdx.x;

    const float4* src = (const float4*)(g_p + (size_t)s0 * NOUT);
    for (int v = tid; v < 8 * NOUT / 4; v += 256)
        ((float4*)sp)[v] = src[v];
    __syncthreads();

    for (int v = tid; v < 8 * NIMU; v += 256) {
        const int i  = v >> 3;
        const int sl = v & 7;
        const int s  = s0 + sl;
        const float* pr = &sp[sl * NOUT];

        float p0  = pr[0 * NIMU + i];
        float p1  = pr[1 * NIMU + i];
        float p2  = pr[2 * NIMU + i];
        float p3  = pr[3 * NIMU + i];
        float c   = pr[4 * NIMU + i];
        float ct  = pr[5 * NIMU + i];
        float phi = pr[6 * NIMU + i];
        float pht = pr[7 * NIMU + i];

        float d  = softplus_f(p1);
        float dt = softplus_f(p3);
        float w1 = sqrtf(softplus_f(p0));
        float w2 = sqrtf(softplus_f(p2));
        float e1 = __expf(-0.5f * d);
        float e2 = __expf(-0.5f * dt);

        float sph, cph, spt, cpt, sw1, cw1, sw2, cw2;
        __sincosf(phi, &sph, &cph);
        __sincosf(pht, &spt, &cpt);
        sincosf(w1, &sw1, &cw1);
        sincosf(w2, &sw2, &cw2);

        const int j = i * SEQ + s;
        g_X0[j] = make_float2(c * cph, ct * cpt);
        g_Y0[j] = make_float2(c * sph, ct * spt);
        g_A[j]  = make_float2(e1 * cw1, e2 * cw2);
        g_B[j]  = make_float2(e1 * sw1, e2 * sw2);

        if (full_out) {
            out[1 * NM + j] = pr[8 * NIMU + i];
            out[2 * NM + j] = softplus_f(pr[9 * NIMU + i]);
            out[3 * NM + j] = pr[10 * NIMU + i];
            out[4 * NM + j] = softplus_f(pr[11 * NIMU + i]);
        }
    }
}

// ---------------------------------------------------------------------------
// 5) Zero kinematics region
// ---------------------------------------------------------------------------
__global__ __launch_bounds__(256) void zero_kernel(float* __restrict__ out) {
    int j = blockIdx.x * 256 + threadIdx.x;
    if (j * 4 < NM) ((float4*)out)[j] = make_float4(0.f, 0.f, 0.f, 0.f);
}

// ---------------------------------------------------------------------------
// 6) Spring + diagonal scatter — rotating-accumulator wavefront (proven).
// ---------------------------------------------------------------------------
__global__ __launch_bounds__(256) void spring_kernel(float* __restrict__ out) {
    __shared__ float sbuf[8][336];

    const int i    = blockIdx.y;
    const int s0   = blockIdx.x * 256;
    const int tid  = threadIdx.x;
    const int w    = tid >> 5;
    const int lane = tid & 31;

    const int s   = s0 + w * 32 + lane;
    const int idx = i * SEQ + s;
    float2 x0 = g_X0[idx], y0 = g_Y0[idx], av = g_A[idx], bv = g_B[idx];
    ull X  = pk2(x0.x, x0.y);
    ull Y  = pk2(y0.x, y0.y);
    ull A  = pk2(av.x, av.y);
    ull B  = pk2(bv.x, bv.y);
    ull Bn = pk2(-bv.x, -bv.y);

    float* buf = &sbuf[w][0];
    float acc = 0.0f;
    int   src = lane;
    int   fl  = -1;

    #pragma unroll 4
    for (int t = 0; t < TSTEPS; t++) {
        float lo, hi;
        upk2(lo, hi, Y);
        float c = lo + hi;
        float r = __shfl_sync(0xffffffffu, c, src);
        if (fl == lane) { buf[t - 1] = acc; acc = 0.0f; }
        acc += r;
        ull u, v, Xn;
        MUL2(u, Y, Bn);
        FMA2(Xn, X, A, u);
        MUL2(v, X, B);
        FMA2(Y, Y, A, v);
        X = Xn;
        src = (src + 31) & 31;
        fl  = (fl + 1) & 31;
    }
    {
        int p = (TSTEPS - 1) + ((lane - ((TSTEPS - 1) & 31)) & 31);
        buf[p] = acc;
    }
    __syncthreads();

    for (int q = tid; q < 555; q += 256) {
        float tot = 0.0f;
        #pragma unroll
        for (int w2 = 0; w2 < 8; w2++) {
            int r = q - 32 * w2;
            if (r >= 0 && r < 331) tot += sbuf[w2][r];
        }
        int pos = s0 + q;
        if (pos < SEQ) atomicAdd(&out[i * SEQ + pos], tot);
    }
}

// ---------------------------------------------------------------------------
// Launch — inputs identified by size
// ---------------------------------------------------------------------------
extern "C" void kernel_launch(void* const* d_in, const int* in_sizes, int n_in,
                              void* d_out, int out_size) {
    const float* x  = nullptr;
    const float* W  = nullptr;
    const float* b  = nullptr;
    const float* v1 = nullptr;
    const float* v2 = nullptr;
    for (int idx = 0; idx < n_in; idx++) {
        int sz = in_sizes[idx];
        const float* p = (const float*)d_in[idx];
        if      (sz == SEQ * DM)   x = p;
        else if (sz == DM * NOUT)  W = p;
        else if (sz == NOUT)       b = p;
        else if (sz == DM)         { if (!v1) v1 = p; else v2 = p; }
    }
    float* out = (float*)d_out;
    int full_out = (out_size >= 5 * NM) ? 1 : 0;

    cudaFuncSetAttribute(gemm_mma_kernel,
                         cudaFuncAttributeMaxDynamicSharedMemorySize,
                         SM_FLOATS * (int)sizeof(float));

    pick_ln_kernel<<<1, 256>>>(v1, v2);
    stats_kernel<<<SEQ, 256>>>(x);
    bprime_kernel<<<NOUT / 32, 256>>>(W, b);
    gemm_mma_kernel<<<dim3(SEQ / BM, NOUT / BN), 256,
                      SM_FLOATS * sizeof(float)>>>(x, W);
    epi_kernel<<<SEQ / 8, 256>>>(out, full_out);
    zero_kernel<<<(NM / 4 + 255) / 256, 256>>>(out);
    spring_kernel<<<dim3(SEQ / 256, NIMU), 256>>>(out);
}